// round 15
// baseline (speedup 1.0000x reference)
#include <cuda_runtime.h>
#include <math.h>

#define NWIN   49
#define DIMC   96
#define HEADS  3
#define HD     32
#define B_TOT  16384
#define NWMASK 1024
#define LDN    52     // padded token dim (multiple of 4, 16B-aligned rows)
#define LDO    100    // padded channel dim (multiple of 4)
#define NT     256
#define SCALE  0.17677669529663687f   // 32^-0.5

// smem layout (floats)
#define OFF_XRT 0          // [96][52]  = 4992
#define OFF_XDT 4992       // [96][52]  = 4992
#define OFF_WT  9984       // [96][100] = 9600
#define OFF_QT  19584      // [96][52]  = 4992
#define OFF_KT  24576      // [96][52]  = 4992
#define OFF_VN  29568      // [49][100] = 4900
#define SMEM_FLOATS 34468
#define SMEM_BYTES  (SMEM_FLOATS * 4)

__device__ float g_bias[HEADS * NWIN * NWIN];

__global__ void bias_init_kernel(const float* __restrict__ table,
                                 const int* __restrict__ rel) {
    int idx = blockIdx.x * blockDim.x + threadIdx.x;
    if (idx < HEADS * NWIN * NWIN) {
        int h = idx / (NWIN * NWIN);
        int r = idx % (NWIN * NWIN);
        g_bias[idx] = table[rel[r] * HEADS + h];
    }
}

// Load x [49][96] from global, store transposed Xt[c][n] (LDN pad)
__device__ __forceinline__ void load_x_t(const float* __restrict__ g,
                                         float* __restrict__ Xt, int tid) {
    for (int t = tid; t < NWIN * 24; t += NT) {
        int n = t / 24, c4 = (t % 24) * 4;
        float4 v = *reinterpret_cast<const float4*>(g + n * DIMC + c4);
        Xt[(c4 + 0) * LDN + n] = v.x;
        Xt[(c4 + 1) * LDN + n] = v.y;
        Xt[(c4 + 2) * LDN + n] = v.z;
        Xt[(c4 + 3) * LDN + n] = v.w;
    }
}

// Load W [96 out][96 in] from global, store transposed Wt[i][o] (LDO pad)
__device__ __forceinline__ void load_w_t(const float* __restrict__ g,
                                         float* __restrict__ Wt, int tid) {
    for (int t = tid; t < DIMC * 24; t += NT) {
        int o = t / 24, c4 = (t % 24) * 4;
        float4 v = *reinterpret_cast<const float4*>(g + o * DIMC + c4);
        Wt[(c4 + 0) * LDO + o] = v.x;
        Wt[(c4 + 1) * LDO + o] = v.y;
        Wt[(c4 + 2) * LDO + o] = v.z;
        Wt[(c4 + 3) * LDO + o] = v.w;
    }
}

// acc[n][o] += sum_i Xt[i][n0..n0+3] * Wt[i][o0..o0+3]
__device__ __forceinline__ void mm96(const float* __restrict__ Xt,
                                     const float* __restrict__ Wt,
                                     int n0, int o0, float (&acc)[4][4]) {
    #pragma unroll 4
    for (int i = 0; i < DIMC; ++i) {
        const float4 xv = *reinterpret_cast<const float4*>(Xt + i * LDN + n0);
        const float4 wv = *reinterpret_cast<const float4*>(Wt + i * LDO + o0);
        const float xs[4] = {xv.x, xv.y, xv.z, xv.w};
        const float ws[4] = {wv.x, wv.y, wv.z, wv.w};
        #pragma unroll
        for (int j = 0; j < 4; ++j)
            #pragma unroll
            for (int jj = 0; jj < 4; ++jj)
                acc[j][jj] = fmaf(xs[j], ws[jj], acc[j][jj]);
    }
}

__global__ __launch_bounds__(NT, 1)
void xattn_kernel(const float* __restrict__ rescaled,
                  const float* __restrict__ rescaler,
                  const float* __restrict__ mask,
                  const float* __restrict__ Wqkv_d,
                  const float* __restrict__ bqkv_d,
                  const float* __restrict__ Wqkv_r,
                  const float* __restrict__ bqkv_r,
                  const float* __restrict__ Wproj,
                  const float* __restrict__ bproj,
                  float* __restrict__ out) {
    extern __shared__ float sm[];
    float* xrt = sm + OFF_XRT;
    float* xdt = sm + OFF_XDT;
    float* Wt  = sm + OFF_WT;
    float* qt  = sm + OFF_QT;   // q transposed [d_global][n]
    float* kt  = sm + OFF_KT;   // k transposed [d_global][n]
    float* vn  = sm + OFF_VN;   // v natural [m][o]
    float* att = sm;            // overlay xrt/xdt: [3*49][LDN] = 7644 <= 9984
    float* ot  = qt;            // AV output transposed, overlays qt

    const int b   = blockIdx.x;
    const int tid = threadIdx.x;
    const float* xg_d = rescaled + (size_t)b * NWIN * DIMC;
    const float* xg_r = rescaler + (size_t)b * NWIN * DIMC;

    load_x_t(xg_r, xrt, tid);
    load_x_t(xg_d, xdt, tid);
    load_w_t(Wqkv_r, Wt, tid);          // q weights: rescaler rows [0,96)
    __syncthreads();

    // ---- q = (xr @ Wq^T + bq) * SCALE, stored transposed ----
    for (int t = tid; t < 13 * 24; t += NT) {
        int to = t % 24, tn = t / 24;
        int n0 = tn * 4, o0 = to * 4;
        float acc[4][4] = {};
        mm96(xrt, Wt, n0, o0, acc);
        float4 bb = *reinterpret_cast<const float4*>(bqkv_r + o0);
        const float bs[4] = {bb.x, bb.y, bb.z, bb.w};
        #pragma unroll
        for (int jj = 0; jj < 4; ++jj)
            #pragma unroll
            for (int j = 0; j < 4; ++j) {
                int n = n0 + j;
                if (n < NWIN) qt[(o0 + jj) * LDN + n] = (acc[j][jj] + bs[jj]) * SCALE;
            }
    }
    __syncthreads();
    load_w_t(Wqkv_d + DIMC * DIMC, Wt, tid);   // k weights: rescaled rows [96,192)
    __syncthreads();

    // ---- k = xd @ Wk^T + bk, stored transposed ----
    for (int t = tid; t < 13 * 24; t += NT) {
        int to = t % 24, tn = t / 24;
        int n0 = tn * 4, o0 = to * 4;
        float acc[4][4] = {};
        mm96(xdt, Wt, n0, o0, acc);
        float4 bb = *reinterpret_cast<const float4*>(bqkv_d + DIMC + o0);
        const float bs[4] = {bb.x, bb.y, bb.z, bb.w};
        #pragma unroll
        for (int jj = 0; jj < 4; ++jj)
            #pragma unroll
            for (int j = 0; j < 4; ++j) {
                int n = n0 + j;
                if (n < NWIN) kt[(o0 + jj) * LDN + n] = acc[j][jj] + bs[jj];
            }
    }
    __syncthreads();
    load_w_t(Wqkv_d + 2 * DIMC * DIMC, Wt, tid);   // v weights: rows [192,288)
    __syncthreads();

    // ---- v = xd @ Wv^T + bv, stored natural [m][o] ----
    for (int t = tid; t < 13 * 24; t += NT) {
        int to = t % 24, tn = t / 24;
        int n0 = tn * 4, o0 = to * 4;
        float acc[4][4] = {};
        mm96(xdt, Wt, n0, o0, acc);
        float4 bb = *reinterpret_cast<const float4*>(bqkv_d + 2 * DIMC + o0);
        #pragma unroll
        for (int j = 0; j < 4; ++j) {
            int n = n0 + j;
            if (n < NWIN) {
                float4 r;
                r.x = acc[j][0] + bb.x;
                r.y = acc[j][1] + bb.y;
                r.z = acc[j][2] + bb.z;
                r.w = acc[j][3] + bb.w;
                *reinterpret_cast<float4*>(vn + n * LDO + o0) = r;
            }
        }
    }
    __syncthreads();

    // Wproj can be staged now (Wt free; attn uses qt/kt only)
    load_w_t(Wproj, Wt, tid);

    // ---- attn[h][n][m] = q.k + bias + mask (overlays xrt/xdt) ----
    const float* mrow = mask + (size_t)(b & (NWMASK - 1)) * NWIN * NWIN;
    for (int t = tid; t < HEADS * 13 * 13; t += NT) {
        int h = t / 169;
        int r = t % 169;
        int n0 = (r / 13) * 4, m0 = (r % 13) * 4;
        float acc[4][4] = {};
        const float* qh = qt + h * HD * LDN;
        const float* kh = kt + h * HD * LDN;
        #pragma unroll 4
        for (int d = 0; d < HD; ++d) {
            const float4 qv = *reinterpret_cast<const float4*>(qh + d * LDN + n0);
            const float4 kv = *reinterpret_cast<const float4*>(kh + d * LDN + m0);
            const float qs[4] = {qv.x, qv.y, qv.z, qv.w};
            const float ks[4] = {kv.x, kv.y, kv.z, kv.w};
            #pragma unroll
            for (int j = 0; j < 4; ++j)
                #pragma unroll
                for (int jj = 0; jj < 4; ++jj)
                    acc[j][jj] = fmaf(qs[j], ks[jj], acc[j][jj]);
        }
        #pragma unroll
        for (int j = 0; j < 4; ++j) {
            int n = n0 + j;
            if (n >= NWIN) continue;
            #pragma unroll
            for (int jj = 0; jj < 4; ++jj) {
                int m = m0 + jj;
                if (m >= NWIN) continue;
                att[(h * NWIN + n) * LDN + m] =
                    acc[j][jj] + g_bias[(h * NWIN + n) * NWIN + m] + mrow[n * NWIN + m];
            }
        }
    }
    __syncthreads();

    // ---- softmax over m, one thread per (h, n) row ----
    for (int r = tid; r < HEADS * NWIN; r += NT) {
        float* row = att + r * LDN;
        float mx = -1e30f;
        #pragma unroll 7
        for (int m = 0; m < NWIN; ++m) mx = fmaxf(mx, row[m]);
        float s = 0.f;
        #pragma unroll 7
        for (int m = 0; m < NWIN; ++m) {
            float e = __expf(row[m] - mx);
            row[m] = e;
            s += e;
        }
        float inv = 1.f / s;
        #pragma unroll 7
        for (int m = 0; m < NWIN; ++m) row[m] *= inv;
    }
    __syncthreads();

    // ---- AV: ot[o][n] = sum_m att[h][n][m] * v[m][o]  (o = h*32+d) ----
    for (int t = tid; t < 13 * 24; t += NT) {
        int to = t % 24, tn = t / 24;
        int n0 = tn * 4, o0 = to * 4;
        int h = o0 / HD;
        float acc[4][4] = {};
        const float* arow = att + (h * NWIN) * LDN;
        #pragma unroll 7
        for (int m = 0; m < NWIN; ++m) {
            const float4 vv = *reinterpret_cast<const float4*>(vn + m * LDO + o0);
            const float vs[4] = {vv.x, vv.y, vv.z, vv.w};
            float a[4];
            #pragma unroll
            for (int j = 0; j < 4; ++j) a[j] = arow[(n0 + j) * LDN + m];
            #pragma unroll
            for (int j = 0; j < 4; ++j)
                #pragma unroll
                for (int jj = 0; jj < 4; ++jj)
                    acc[j][jj] = fmaf(a[j], vs[jj], acc[j][jj]);
        }
        #pragma unroll
        for (int jj = 0; jj < 4; ++jj)
            #pragma unroll
            for (int j = 0; j < 4; ++j) {
                int n = n0 + j;
                if (n < NWIN) ot[(o0 + jj) * LDN + n] = acc[j][jj];
            }
    }
    __syncthreads();

    // ---- proj: out[n][c] = sum_i ot[i][n] * Wproj[c][i] + bproj[c] ----
    float* og = out + (size_t)b * NWIN * DIMC;
    for (int t = tid; t < 13 * 24; t += NT) {
        int to = t % 24, tn = t / 24;
        int n0 = tn * 4, o0 = to * 4;
        float acc[4][4] = {};
        mm96(ot, Wt, n0, o0, acc);
        float4 bb = *reinterpret_cast<const float4*>(bproj + o0);
        #pragma unroll
        for (int j = 0; j < 4; ++j) {
            int n = n0 + j;
            if (n < NWIN) {
                float4 r;
                r.x = acc[j][0] + bb.x;
                r.y = acc[j][1] + bb.y;
                r.z = acc[j][2] + bb.z;
                r.w = acc[j][3] + bb.w;
                *reinterpret_cast<float4*>(og + n * DIMC + o0) = r;
            }
        }
    }
}

extern "C" void kernel_launch(void* const* d_in, const int* in_sizes, int n_in,
                              void* d_out, int out_size) {
    const float* rescaled = (const float*)d_in[0];
    const float* rescaler = (const float*)d_in[1];
    const float* mask     = (const float*)d_in[2];
    const float* Wqkv_d   = (const float*)d_in[3];
    const float* bqkv_d   = (const float*)d_in[4];
    const float* Wqkv_r   = (const float*)d_in[5];
    const float* bqkv_r   = (const float*)d_in[6];
    const float* table    = (const float*)d_in[7];
    const float* Wproj    = (const float*)d_in[8];
    const float* bproj    = (const float*)d_in[9];
    const int*   rel      = (const int*)d_in[10];
    float* out = (float*)d_out;

    cudaFuncSetAttribute(xattn_kernel,
                         cudaFuncAttributeMaxDynamicSharedMemorySize, SMEM_BYTES);

    bias_init_kernel<<<(HEADS * NWIN * NWIN + 255) / 256, 256>>>(table, rel);
    xattn_kernel<<<B_TOT, NT, SMEM_BYTES>>>(rescaled, rescaler, mask,
                                            Wqkv_d, bqkv_d, Wqkv_r, bqkv_r,
                                            Wproj, bproj, out);
}

// round 16
// speedup vs baseline: 1.0052x; 1.0052x over previous
#include <cuda_runtime.h>
#include <math.h>

#define NWIN   49
#define DIMC   96
#define HEADS  3
#define HD     32
#define B_TOT  16384
#define NWMASK 1024
#define LDN    52     // padded token dim (multiple of 4, 16B-aligned rows)
#define LDO    100    // padded channel dim (multiple of 4)
#define NT     256
#define SCALE  0.17677669529663687f   // 32^-0.5

// smem layout (floats)
#define OFF_XRT 0          // [96][52]  = 4992
#define OFF_XDT 4992       // [96][52]  = 4992
#define OFF_WT  9984       // [96][100] = 9600
#define OFF_QT  19584      // [96][52]  = 4992
#define OFF_KT  24576      // [96][52]  = 4992
#define OFF_VN  29568      // [49][100] = 4900
#define SMEM_FLOATS 34468
#define SMEM_BYTES  (SMEM_FLOATS * 4)

__device__ float g_bias[HEADS * NWIN * NWIN];

__global__ void bias_init_kernel(const float* __restrict__ table,
                                 const int* __restrict__ rel) {
    int idx = blockIdx.x * blockDim.x + threadIdx.x;
    if (idx < HEADS * NWIN * NWIN) {
        int h = idx / (NWIN * NWIN);
        int r = idx % (NWIN * NWIN);
        g_bias[idx] = table[rel[r] * HEADS + h];
    }
}

// Load x [49][96] from global, store transposed Xt[c][n] (LDN pad)
__device__ __forceinline__ void load_x_t(const float* __restrict__ g,
                                         float* __restrict__ Xt, int tid) {
    for (int t = tid; t < NWIN * 24; t += NT) {
        int n = t / 24, c4 = (t % 24) * 4;
        float4 v = *reinterpret_cast<const float4*>(g + n * DIMC + c4);
        Xt[(c4 + 0) * LDN + n] = v.x;
        Xt[(c4 + 1) * LDN + n] = v.y;
        Xt[(c4 + 2) * LDN + n] = v.z;
        Xt[(c4 + 3) * LDN + n] = v.w;
    }
}

// Load W [96 out][96 in] from global, store transposed Wt[i][o] (LDO pad)
__device__ __forceinline__ void load_w_t(const float* __restrict__ g,
                                         float* __restrict__ Wt, int tid) {
    for (int t = tid; t < DIMC * 24; t += NT) {
        int o = t / 24, c4 = (t % 24) * 4;
        float4 v = *reinterpret_cast<const float4*>(g + o * DIMC + c4);
        Wt[(c4 + 0) * LDO + o] = v.x;
        Wt[(c4 + 1) * LDO + o] = v.y;
        Wt[(c4 + 2) * LDO + o] = v.z;
        Wt[(c4 + 3) * LDO + o] = v.w;
    }
}

// acc[n][o] += sum_i Xt[i][n0..n0+3] * Wt[i][o0..o0+3]
__device__ __forceinline__ void mm96(const float* __restrict__ Xt,
                                     const float* __restrict__ Wt,
                                     int n0, int o0, float (&acc)[4][4]) {
    #pragma unroll 4
    for (int i = 0; i < DIMC; ++i) {
        const float4 xv = *reinterpret_cast<const float4*>(Xt + i * LDN + n0);
        const float4 wv = *reinterpret_cast<const float4*>(Wt + i * LDO + o0);
        const float xs[4] = {xv.x, xv.y, xv.z, xv.w};
        const float ws[4] = {wv.x, wv.y, wv.z, wv.w};
        #pragma unroll
        for (int j = 0; j < 4; ++j)
            #pragma unroll
            for (int jj = 0; jj < 4; ++jj)
                acc[j][jj] = fmaf(xs[j], ws[jj], acc[j][jj]);
    }
}

__global__ __launch_bounds__(NT, 1)
void xattn_kernel(const float* __restrict__ rescaled,
                  const float* __restrict__ rescaler,
                  const float* __restrict__ mask,
                  const float* __restrict__ Wqkv_d,
                  const float* __restrict__ bqkv_d,
                  const float* __restrict__ Wqkv_r,
                  const float* __restrict__ bqkv_r,
                  const float* __restrict__ Wproj,
                  const float* __restrict__ bproj,
                  float* __restrict__ out) {
    extern __shared__ float sm[];
    float* xrt = sm + OFF_XRT;
    float* xdt = sm + OFF_XDT;
    float* Wt  = sm + OFF_WT;
    float* qt  = sm + OFF_QT;   // q transposed [d_global][n]
    float* kt  = sm + OFF_KT;   // k transposed [d_global][n]
    float* vn  = sm + OFF_VN;   // v natural [m][o]
    float* att = sm;            // overlay xrt/xdt: [3*49][LDN] = 7644 <= 9984
    float* ot  = qt;            // AV output transposed, overlays qt

    const int b   = blockIdx.x;
    const int tid = threadIdx.x;
    const float* xg_d = rescaled + (size_t)b * NWIN * DIMC;
    const float* xg_r = rescaler + (size_t)b * NWIN * DIMC;

    load_x_t(xg_r, xrt, tid);
    load_x_t(xg_d, xdt, tid);
    load_w_t(Wqkv_r, Wt, tid);          // q weights: rescaler rows [0,96)
    __syncthreads();

    // ---- q = (xr @ Wq^T + bq) * SCALE, stored transposed ----
    for (int t = tid; t < 13 * 24; t += NT) {
        int to = t % 24, tn = t / 24;
        int n0 = tn * 4, o0 = to * 4;
        float acc[4][4] = {};
        mm96(xrt, Wt, n0, o0, acc);
        float4 bb = *reinterpret_cast<const float4*>(bqkv_r + o0);
        const float bs[4] = {bb.x, bb.y, bb.z, bb.w};
        #pragma unroll
        for (int jj = 0; jj < 4; ++jj)
            #pragma unroll
            for (int j = 0; j < 4; ++j) {
                int n = n0 + j;
                if (n < NWIN) qt[(o0 + jj) * LDN + n] = (acc[j][jj] + bs[jj]) * SCALE;
            }
    }
    __syncthreads();
    load_w_t(Wqkv_d + DIMC * DIMC, Wt, tid);   // k weights: rescaled rows [96,192)
    __syncthreads();

    // ---- k = xd @ Wk^T + bk, stored transposed ----
    for (int t = tid; t < 13 * 24; t += NT) {
        int to = t % 24, tn = t / 24;
        int n0 = tn * 4, o0 = to * 4;
        float acc[4][4] = {};
        mm96(xdt, Wt, n0, o0, acc);
        float4 bb = *reinterpret_cast<const float4*>(bqkv_d + DIMC + o0);
        const float bs[4] = {bb.x, bb.y, bb.z, bb.w};
        #pragma unroll
        for (int jj = 0; jj < 4; ++jj)
            #pragma unroll
            for (int j = 0; j < 4; ++j) {
                int n = n0 + j;
                if (n < NWIN) kt[(o0 + jj) * LDN + n] = acc[j][jj] + bs[jj];
            }
    }
    __syncthreads();
    load_w_t(Wqkv_d + 2 * DIMC * DIMC, Wt, tid);   // v weights: rows [192,288)
    __syncthreads();

    // ---- v = xd @ Wv^T + bv, stored natural [m][o] ----
    for (int t = tid; t < 13 * 24; t += NT) {
        int to = t % 24, tn = t / 24;
        int n0 = tn * 4, o0 = to * 4;
        float acc[4][4] = {};
        mm96(xdt, Wt, n0, o0, acc);
        float4 bb = *reinterpret_cast<const float4*>(bqkv_d + 2 * DIMC + o0);
        #pragma unroll
        for (int j = 0; j < 4; ++j) {
            int n = n0 + j;
            if (n < NWIN) {
                float4 r;
                r.x = acc[j][0] + bb.x;
                r.y = acc[j][1] + bb.y;
                r.z = acc[j][2] + bb.z;
                r.w = acc[j][3] + bb.w;
                *reinterpret_cast<float4*>(vn + n * LDO + o0) = r;
            }
        }
    }
    __syncthreads();

    // Wproj can be staged now (Wt free; attn uses qt/kt only)
    load_w_t(Wproj, Wt, tid);

    // ---- attn[h][n][m] = q.k + bias + mask (overlays xrt/xdt) ----
    const float* mrow = mask + (size_t)(b & (NWMASK - 1)) * NWIN * NWIN;
    for (int t = tid; t < HEADS * 13 * 13; t += NT) {
        int h = t / 169;
        int r = t % 169;
        int n0 = (r / 13) * 4, m0 = (r % 13) * 4;
        float acc[4][4] = {};
        const float* qh = qt + h * HD * LDN;
        const float* kh = kt + h * HD * LDN;
        #pragma unroll 4
        for (int d = 0; d < HD; ++d) {
            const float4 qv = *reinterpret_cast<const float4*>(qh + d * LDN + n0);
            const float4 kv = *reinterpret_cast<const float4*>(kh + d * LDN + m0);
            const float qs[4] = {qv.x, qv.y, qv.z, qv.w};
            const float ks[4] = {kv.x, kv.y, kv.z, kv.w};
            #pragma unroll
            for (int j = 0; j < 4; ++j)
                #pragma unroll
                for (int jj = 0; jj < 4; ++jj)
                    acc[j][jj] = fmaf(qs[j], ks[jj], acc[j][jj]);
        }
        #pragma unroll
        for (int j = 0; j < 4; ++j) {
            int n = n0 + j;
            if (n >= NWIN) continue;
            #pragma unroll
            for (int jj = 0; jj < 4; ++jj) {
                int m = m0 + jj;
                if (m >= NWIN) continue;
                att[(h * NWIN + n) * LDN + m] =
                    acc[j][jj] + g_bias[(h * NWIN + n) * NWIN + m] + mrow[n * NWIN + m];
            }
        }
    }
    __syncthreads();

    // ---- softmax over m, one thread per (h, n) row ----
    for (int r = tid; r < HEADS * NWIN; r += NT) {
        float* row = att + r * LDN;
        float mx = -1e30f;
        #pragma unroll 7
        for (int m = 0; m < NWIN; ++m) mx = fmaxf(mx, row[m]);
        float s = 0.f;
        #pragma unroll 7
        for (int m = 0; m < NWIN; ++m) {
            float e = __expf(row[m] - mx);
            row[m] = e;
            s += e;
        }
        float inv = 1.f / s;
        #pragma unroll 7
        for (int m = 0; m < NWIN; ++m) row[m] *= inv;
    }
    __syncthreads();

    // ---- AV: ot[o][n] = sum_m att[h][n][m] * v[m][o]  (o = h*32+d) ----
    for (int t = tid; t < 13 * 24; t += NT) {
        int to = t % 24, tn = t / 24;
        int n0 = tn * 4, o0 = to * 4;
        int h = o0 / HD;
        float acc[4][4] = {};
        const float* arow = att + (h * NWIN) * LDN;
        #pragma unroll 7
        for (int m = 0; m < NWIN; ++m) {
            const float4 vv = *reinterpret_cast<const float4*>(vn + m * LDO + o0);
            const float vs[4] = {vv.x, vv.y, vv.z, vv.w};
            float a[4];
            #pragma unroll
            for (int j = 0; j < 4; ++j) a[j] = arow[(n0 + j) * LDN + m];
            #pragma unroll
            for (int j = 0; j < 4; ++j)
                #pragma unroll
                for (int jj = 0; jj < 4; ++jj)
                    acc[j][jj] = fmaf(a[j], vs[jj], acc[j][jj]);
        }
        #pragma unroll
        for (int jj = 0; jj < 4; ++jj)
            #pragma unroll
            for (int j = 0; j < 4; ++j) {
                int n = n0 + j;
                if (n < NWIN) ot[(o0 + jj) * LDN + n] = acc[j][jj];
            }
    }
    __syncthreads();

    // ---- proj: out[n][c] = sum_i ot[i][n] * Wproj[c][i] + bproj[c] ----
    float* og = out + (size_t)b * NWIN * DIMC;
    for (int t = tid; t < 13 * 24; t += NT) {
        int to = t % 24, tn = t / 24;
        int n0 = tn * 4, o0 = to * 4;
        float acc[4][4] = {};
        mm96(ot, Wt, n0, o0, acc);
        float4 bb = *reinterpret_cast<const float4*>(bproj + o0);
        #pragma unroll
        for (int j = 0; j < 4; ++j) {
            int n = n0 + j;
            if (n < NWIN) {
                float4 r;
                r.x = acc[j][0] + bb.x;
                r.y = acc[j][1] + bb.y;
                r.z = acc[j][2] + bb.z;
                r.w = acc[j][3] + bb.w;
                *reinterpret_cast<float4*>(og + n * DIMC + o0) = r;
            }
        }
    }
}

extern "C" void kernel_launch(void* const* d_in, const int* in_sizes, int n_in,
                              void* d_out, int out_size) {
    const float* rescaled = (const float*)d_in[0];
    const float* rescaler = (const float*)d_in[1];
    const float* mask     = (const float*)d_in[2];
    const float* Wqkv_d   = (const float*)d_in[3];
    const float* bqkv_d   = (const float*)d_in[4];
    const float* Wqkv_r   = (const float*)d_in[5];
    const float* bqkv_r   = (const float*)d_in[6];
    const float* table    = (const float*)d_in[7];
    const float* Wproj    = (const float*)d_in[8];
    const float* bproj    = (const float*)d_in[9];
    const int*   rel      = (const int*)d_in[10];
    float* out = (float*)d_out;

    cudaFuncSetAttribute(xattn_kernel,
                         cudaFuncAttributeMaxDynamicSharedMemorySize, SMEM_BYTES);

    bias_init_kernel<<<(HEADS * NWIN * NWIN + 255) / 256, 256>>>(table, rel);
    xattn_kernel<<<B_TOT, NT, SMEM_BYTES>>>(rescaled, rescaler, mask,
                                            Wqkv_d, bqkv_d, Wqkv_r, bqkv_r,
                                            Wproj, bproj, out);
}